// round 16
// baseline (speedup 1.0000x reference)
#include <cuda_runtime.h>
#include <cuda_fp16.h>
#include <cstdint>
#include <cstddef>

// Problem constants
#define BWT   1024
#define WIN_  128
#define CH    512
#define NHH   8
#define HDD   64
#define MROWS (BWT * WIN_)   // 131072
#define N1    (3 * CH)       // 1536
#define KC    512

// ---------------- scratch (device globals) ----------------------------------
__device__ __half g_qkvh[(size_t)MROWS * N1];  // fp16 qkv (GEMM1 out, attn in)
__device__ __half g_xh[(size_t)MROWS * KC];    // fp16(x)
__device__ __half g_ath[(size_t)MROWS * CH];   // fp16 attention out
__device__ __half g_wqh[(size_t)N1 * KC];      // fp16(w_qkv^T)  [N1][K]
__device__ __half g_wph[(size_t)CH * KC];      // fp16(w_proj^T) [CH][K]
__device__ int    g_cnt[BWT];                  // per-window attn completion count

// ---------------- helpers ----------------------------------------------------
__device__ __forceinline__ uint32_t smem_u32(const void* p) {
    uint32_t a;
    asm("{ .reg .u64 t; cvta.to.shared.u64 t, %1; cvt.u32.u64 %0, t; }" : "=r"(a) : "l"(p));
    return a;
}

#define CP_ASYNC16(dst, src) \
    asm volatile("cp.async.cg.shared.global [%0], [%1], 16;" :: "r"(dst), "l"(src) : "memory")
#define CP_COMMIT()  asm volatile("cp.async.commit_group;" ::: "memory")
#define CP_WAIT2()   asm volatile("cp.async.wait_group 2;" ::: "memory")
#define CP_WAIT1()   asm volatile("cp.async.wait_group 1;" ::: "memory")
#define CP_WAIT0()   asm volatile("cp.async.wait_group 0;" ::: "memory")

#define LDM4(r0, r1, r2, r3, addr) \
    asm volatile("ldmatrix.sync.aligned.m8n8.x4.shared.b16 {%0,%1,%2,%3}, [%4];" \
        : "=r"(r0), "=r"(r1), "=r"(r2), "=r"(r3) : "r"(addr))
#define LDM4T(r0, r1, r2, r3, addr) \
    asm volatile("ldmatrix.sync.aligned.m8n8.x4.trans.shared.b16 {%0,%1,%2,%3}, [%4];" \
        : "=r"(r0), "=r"(r1), "=r"(r2), "=r"(r3) : "r"(addr))

#define MMA_F16(d, a, b0, b1) \
    asm volatile("mma.sync.aligned.m16n8k16.row.col.f32.f16.f16.f32 " \
        "{%0,%1,%2,%3}, {%4,%5,%6,%7}, {%8,%9}, {%0,%1,%2,%3};" \
        : "+f"((d)[0]), "+f"((d)[1]), "+f"((d)[2]), "+f"((d)[3]) \
        : "r"((a)[0]), "r"((a)[1]), "r"((a)[2]), "r"((a)[3]), "r"(b0), "r"(b1))

__device__ __forceinline__ uint32_t h2u(float a, float b) {
    __half2 h = __floats2half2_rn(a, b);
    return *(uint32_t*)&h;
}
__device__ __forceinline__ void store2(float* p, float a, float b) {
    *(float2*)p = make_float2(a, b);
}
__device__ __forceinline__ void store2(__half* p, float a, float b) {
    *(__half2*)p = __floats2half2_rn(a, b);
}

// ---------------- prepass: x -> fp16 ------------------------------------------
__global__ void conv_h(const float* __restrict__ in, __half* __restrict__ o) {
    size_t i = ((size_t)blockIdx.x * blockDim.x + threadIdx.x) * 4;
    float4 v = *(const float4*)(in + i);
    __half h[4] = {__float2half_rn(v.x), __float2half_rn(v.y),
                   __float2half_rn(v.z), __float2half_rn(v.w)};
    *(uint2*)(o + i) = *(uint2*)h;
}

// ---------------- prepass: transpose weights -> fp16 [N][K] -------------------
__global__ void transpose_h(const float* __restrict__ W,
                            __half* __restrict__ Th, int K, int N) {
    __shared__ float t[32][33];
    int kb = blockIdx.y * 32, nb = blockIdx.x * 32;
    for (int i = threadIdx.y; i < 32; i += 8)
        t[i][threadIdx.x] = W[(size_t)(kb + i) * N + nb + threadIdx.x];
    __syncthreads();
    for (int i = threadIdx.y; i < 32; i += 8)
        Th[(size_t)(nb + i) * K + kb + threadIdx.x] = __float2half_rn(t[threadIdx.x][i]);
}

// ---------------- GEMM1 (R11 measured-best): qkv = x @ w_qkv^T + b -----------
// CTA 128x128, BK=64, 128 threads (4 warps 2x2, warp tile 64x64), 3-stage,
// 2 CTAs/SM.
#define STAGE_B 32768
#define GEMM_SMEM (3 * STAGE_B)

__global__ __launch_bounds__(128, 2)
void gemm_mma(const __half* __restrict__ Ah, const __half* __restrict__ Bh,
              const float* __restrict__ bias, __half* __restrict__ C, int N)
{
    extern __shared__ char smem[];
    const uint32_t sbase = smem_u32(smem);
    const int tid = threadIdx.x;
    const int lane = tid & 31, wid = tid >> 5;
    const int wm = wid & 1, wn = wid >> 1;
    const size_t m0 = (size_t)blockIdx.y * 128;
    const size_t n0 = (size_t)blockIdx.x * 128;

    const int r0 = tid >> 3, c = tid & 7;
    const __half* srcA = Ah + (m0 + r0) * KC + c * 8;
    const __half* srcB = Bh + (n0 + r0) * KC + c * 8;
    const uint32_t dstA = sbase + r0 * 128 + (uint32_t)((c ^ (r0 & 7)) << 4);
    const uint32_t dstB = dstA + 16384;

#define LOAD_PART(buf, k0, T0, T1) do {                                  \
        uint32_t so = (uint32_t)(buf) * STAGE_B;                         \
        _Pragma("unroll")                                                \
        for (int t = (T0); t < (T1); t++) {                              \
            CP_ASYNC16(dstA + so + t * 2048, srcA + (k0) + t * 16 * KC); \
            CP_ASYNC16(dstB + so + t * 2048, srcB + (k0) + t * 16 * KC); \
        }                                                                \
    } while (0)

    const int arow = wm * 64 + (lane & 15);
    const int brow_ = wn * 64 + (lane & 7) + ((lane >> 4) << 3);
#define LD_AFRAG(fa, stb, slab) do {                                       \
        _Pragma("unroll")                                                  \
        for (int mi = 0; mi < 4; mi++) {                                   \
            int row = arow + mi * 16;                                      \
            int kc = ((slab) << 1) + (lane >> 4);                          \
            LDM4((fa)[mi][0], (fa)[mi][1], (fa)[mi][2], (fa)[mi][3],       \
                 (stb) + row * 128 + ((kc ^ (row & 7)) << 4));             \
        }                                                                  \
    } while (0)
#define LD_BFRAG(bh, stb, slab) do {                                       \
        _Pragma("unroll")                                                  \
        for (int nj = 0; nj < 4; nj++) {                                   \
            int row = brow_ + nj * 16;                                     \
            int kc = ((slab) << 1) + ((lane >> 3) & 1);                    \
            LDM4((bh)[nj][0], (bh)[nj][1], (bh)[nj][2], (bh)[nj][3],       \
                 (stb) + 16384 + row * 128 + ((kc ^ (row & 7)) << 4));     \
        }                                                                  \
    } while (0)

    float D[4][8][4];
#pragma unroll
    for (int i = 0; i < 4; i++)
#pragma unroll
        for (int j = 0; j < 8; j++)
#pragma unroll
            for (int q = 0; q < 4; q++) D[i][j][q] = 0.0f;

    LOAD_PART(0, 0, 0, 8);  CP_COMMIT();
    LOAD_PART(1, 64, 0, 8); CP_COMMIT();

    uint32_t fa[2][4][4], fb[2][4][4];

    const int NSTAGE = KC / 64;   // 8
#pragma unroll 1
    for (int s = 0; s < NSTAGE; s++) {
        if (s + 1 < NSTAGE) { CP_WAIT1(); } else { CP_WAIT0(); }
        __syncthreads();

        int bufc = s; bufc -= (bufc >= 3) ? 3 : 0; bufc -= (bufc >= 3) ? 3 : 0;
        bufc -= (bufc >= 3) ? 3 : 0;
        const uint32_t stb = sbase + (uint32_t)bufc * STAGE_B;

        const bool havenext = (s + 2 < NSTAGE);
        int nb = s + 2; nb -= (nb >= 3) ? 3 : 0; nb -= (nb >= 3) ? 3 : 0;
        const int nk0 = (s + 2) * 64;

        LD_BFRAG(fb[0], stb, 0);
        LD_AFRAG(fa[0], stb, 0);
        if (havenext) LOAD_PART(nb, nk0, 0, 4);

#pragma unroll
        for (int slab = 0; slab < 4; slab++) {
            const int cur = slab & 1, nxt = cur ^ 1;
            if (slab < 3) {
                LD_BFRAG(fb[nxt], stb, slab + 1);
                LD_AFRAG(fa[nxt], stb, slab + 1);
            }
#pragma unroll
            for (int mi = 0; mi < 4; mi++)
#pragma unroll
                for (int n8 = 0; n8 < 8; n8++) {
                    const int nj = n8 >> 1, hb = (n8 & 1) * 2;
                    MMA_F16(D[mi][n8], fa[cur][mi], fb[cur][nj][hb], fb[cur][nj][hb + 1]);
                }
            if (slab == 0 && havenext) { LOAD_PART(nb, nk0, 4, 8); CP_COMMIT(); }
        }
    }

    const int gr = lane >> 2, tg = lane & 3;
#pragma unroll
    for (int mi = 0; mi < 4; mi++) {
        size_t rowa = m0 + wm * 64 + mi * 16 + gr;
#pragma unroll
        for (int n8 = 0; n8 < 8; n8++) {
            int col = (int)n0 + wn * 64 + n8 * 8 + tg * 2;
            float b0v = bias[col], b1v = bias[col + 1];
            store2(C + rowa * N + col, D[mi][n8][0] + b0v, D[mi][n8][1] + b1v);
            store2(C + (rowa + 8) * N + col, D[mi][n8][2] + b0v, D[mi][n8][3] + b1v);
        }
    }
}

// ---------------- fused attn + proj with per-window dependency counter -------
// Blocks [0, 8192): attention (b = blk>>3, h = blk&7)  -> att gmem, cnt[b]++
// Blocks [8192, 12288): GEMM2 tile (win = idx>>2, nblk = idx&3), spins on
//   cnt[win]==8 then computes out[win rows] = att @ w_proj^T + b_proj.
// 256 threads, 64KB dynamic smem, 2 CTAs/SM for both roles.
#define FUSE_SMEM 65536

__global__ __launch_bounds__(256, 2)
void attn_proj(const __half* __restrict__ qkv, const float* __restrict__ mask,
               const float* __restrict__ btab, __half* __restrict__ att,
               const __half* __restrict__ wp, const float* __restrict__ bproj,
               float* __restrict__ out)
{
    extern __shared__ char smc[];
    const uint32_t sb = smem_u32(smc);
    const int tid = threadIdx.x;
    const int lane = tid & 31, w = tid >> 5;
    const int gr = lane >> 2, tg = lane & 3;

    if (blockIdx.x < 8 * BWT) {
        // ================= attention role (R15 kernel) =================
        const int h = blockIdx.x & 7;
        const int b = blockIdx.x >> 3;

        const uint32_t Qb = sb;
        const uint32_t Kb = sb + 16384;
        const uint32_t Vb = sb + 32768;
        float* bs = (float*)(smc + 49152);

        const size_t grow0 = (size_t)b * WIN_;
#pragma unroll
        for (int i = 0; i < 4; i++) {
            int g = tid + 256 * i;
            int r = g >> 3, c = g & 7;
            const __half* src = qkv + (grow0 + r) * N1 + h * HDD + c * 8;
            uint32_t doff = r * 128 + (uint32_t)((c ^ (r & 7)) << 4);
            CP_ASYNC16(Qb + doff, src);
            CP_ASYNC16(Kb + doff, src + CH);
            CP_ASYNC16(Vb + doff, src + 2 * CH);
        }
        CP_COMMIT();
        if (tid < 255) bs[tid] = btab[tid * NHH + h];
        CP_WAIT0();
        __syncthreads();

        const int m0 = w * 16;
        const int r_lo = m0 + gr, r_hi = m0 + gr + 8;

        float D[16][4];
#pragma unroll
        for (int j = 0; j < 16; j++)
#pragma unroll
            for (int c2 = 0; c2 < 4; c2++) D[j][c2] = 0.0f;

#pragma unroll
        for (int s = 0; s < 4; s++) {
            uint32_t a[4];
            {
                int row = m0 + (lane & 15);
                int kc = (s << 1) + (lane >> 4);
                LDM4(a[0], a[1], a[2], a[3], Qb + row * 128 + ((kc ^ (row & 7)) << 4));
            }
#pragma unroll
            for (int jj = 0; jj < 8; jj++) {
                uint32_t v0, v1, v2, v3;
                int grp = lane >> 3;
                int nrow = jj * 16 + ((grp >> 1) & 1) * 8 + (lane & 7);
                int kc = (s << 1) + (grp & 1);
                LDM4(v0, v1, v2, v3, Kb + nrow * 128 + ((kc ^ (nrow & 7)) << 4));
                MMA_F16(D[2 * jj], a, v0, v1);
                MMA_F16(D[2 * jj + 1], a, v2, v3);
            }
        }

        const float* mrow = mask + (size_t)(b & 63) * (WIN_ * WIN_);
        uint32_t Pk[16][2];
        float slo = 0.0f, shi = 0.0f;
#pragma unroll
        for (int j = 0; j < 16; j++) {
            int c = 8 * j + 2 * tg;
            float2 mlo2 = *(const float2*)(mrow + r_lo * 128 + c);
            float2 mhi2 = *(const float2*)(mrow + r_hi * 128 + c);
            float e0 = __expf(D[j][0] * 0.125f + bs[c - r_lo + 127] + mlo2.x);
            float e1 = __expf(D[j][1] * 0.125f + bs[c + 1 - r_lo + 127] + mlo2.y);
            float e2 = __expf(D[j][2] * 0.125f + bs[c - r_hi + 127] + mhi2.x);
            float e3 = __expf(D[j][3] * 0.125f + bs[c + 1 - r_hi + 127] + mhi2.y);
            slo += e0 + e1;
            shi += e2 + e3;
            Pk[j][0] = h2u(e0, e1);
            Pk[j][1] = h2u(e2, e3);
        }
        slo += __shfl_xor_sync(0xffffffffu, slo, 1);
        slo += __shfl_xor_sync(0xffffffffu, slo, 2);
        shi += __shfl_xor_sync(0xffffffffu, shi, 1);
        shi += __shfl_xor_sync(0xffffffffu, shi, 2);
        const float invlo = 1.0f / slo, invhi = 1.0f / shi;

        float O[8][4];
#pragma unroll
        for (int j = 0; j < 8; j++)
#pragma unroll
            for (int c2 = 0; c2 < 4; c2++) O[j][c2] = 0.0f;

#pragma unroll
        for (int s = 0; s < 8; s++) {
            uint32_t a[4];
            a[0] = Pk[2 * s][0];
            a[1] = Pk[2 * s][1];
            a[2] = Pk[2 * s + 1][0];
            a[3] = Pk[2 * s + 1][1];
#pragma unroll
            for (int jj = 0; jj < 4; jj++) {
                uint32_t v0, v1, v2, v3;
                int grp = lane >> 3;
                int krow = 16 * s + (grp & 1) * 8 + (lane & 7);
                int nc = (jj << 1) + ((grp >> 1) & 1);
                LDM4T(v0, v1, v2, v3, Vb + krow * 128 + ((nc ^ (krow & 7)) << 4));
                MMA_F16(O[2 * jj], a, v0, v1);
                MMA_F16(O[2 * jj + 1], a, v2, v3);
            }
        }

        __half* ob = att + grow0 * CH + h * HDD;
#pragma unroll
        for (int j = 0; j < 8; j++) {
            int c = 8 * j + 2 * tg;
            *(__half2*)(ob + (size_t)r_lo * CH + c) =
                __floats2half2_rn(O[j][0] * invlo, O[j][1] * invlo);
            *(__half2*)(ob + (size_t)r_hi * CH + c) =
                __floats2half2_rn(O[j][2] * invhi, O[j][3] * invhi);
        }

        __threadfence();
        __syncthreads();
        if (tid == 0) atomicAdd(&g_cnt[b], 1);
        return;
    }

    // ================= GEMM2 role (R8 config, 64x32 warp tiles) =================
    const int idx = blockIdx.x - 8 * BWT;
    const int win = idx >> 2;
    const size_t m0 = (size_t)win * 128;
    const size_t n0 = (size_t)(idx & 3) * 128;
    const int wm = w & 1, wn = w >> 1;   // 2 x 4 warp grid

    // wait for this window's 8 attention CTAs
    if (tid == 0) {
        volatile int* c = g_cnt + win;
        while (*c != 8) __nanosleep(128);
        __threadfence();
    }
    __syncthreads();

    const __half* Ah = att;
    const __half* Bh = wp;

    // loader: 256 rows x 64B per stage = 1024 16B-chunks; 4 per thread
    const __half* srcp[4];
    uint32_t      dstp[4];
#pragma unroll
    for (int t = 0; t < 4; t++) {
        int g = tid + 256 * t;
        int row = g >> 2, c = g & 3;
        int mat = row >> 7, r = row & 127;
        srcp[t] = (mat ? Bh + (n0 + r) * KC : Ah + (m0 + r) * KC) + c * 8;
        dstp[t] = sb + mat * 8192 + r * 64 + (uint32_t)((c ^ ((r >> 1) & 3)) << 4);
    }

#define G2_LOAD(buf, k0) do {                                      \
        uint32_t so = (uint32_t)(buf) * 16384;                     \
        _Pragma("unroll")                                          \
        for (int t = 0; t < 4; t++)                                \
            CP_ASYNC16(dstp[t] + so, srcp[t] + (k0));              \
    } while (0)

    float D[4][4][4];
#pragma unroll
    for (int i = 0; i < 4; i++)
#pragma unroll
        for (int j = 0; j < 4; j++)
#pragma unroll
            for (int q = 0; q < 4; q++) D[i][j][q] = 0.0f;

    G2_LOAD(0, 0);  CP_COMMIT();
    G2_LOAD(1, 32); CP_COMMIT();
    G2_LOAD(2, 64); CP_COMMIT();

    const int NST2 = KC / 32;   // 16
    int buf = 0;
#pragma unroll 1
    for (int s = 0; s < NST2; s++) {
        CP_WAIT2();
        __syncthreads();

        if (s + 3 < NST2) {
            G2_LOAD((buf + 3) & 3, (s + 3) * 32);
            CP_COMMIT();
        }

        const uint32_t stb = sb + (uint32_t)buf * 16384;

#pragma unroll
        for (int slab = 0; slab < 2; slab++) {
            uint32_t bh4[2][4];
#pragma unroll
            for (int nj = 0; nj < 2; nj++) {
                int row = wn * 32 + nj * 16 + (lane & 7) + ((lane >> 4) << 3);
                int c16 = ((slab << 1) + ((lane >> 3) & 1)) ^ ((row >> 1) & 3);
                LDM4(bh4[nj][0], bh4[nj][1], bh4[nj][2], bh4[nj][3],
                     stb + 8192 + row * 64 + c16 * 16);
            }
            uint32_t fa[4][4];
#pragma unroll
            for (int mi = 0; mi < 4; mi++) {
                int row = wm * 64 + mi * 16 + (lane & 15);
                int c16 = ((slab << 1) + (lane >> 4)) ^ ((row >> 1) & 3);
                LDM4(fa[mi][0], fa[mi][1], fa[mi][2], fa[mi][3],
                     stb + row * 64 + c16 * 16);
            }
#pragma unroll
            for (int mi = 0; mi < 4; mi++)
#pragma unroll
                for (int n8 = 0; n8 < 4; n8++) {
                    const int nj = n8 >> 1, hb = (n8 & 1) * 2;
                    MMA_F16(D[mi][n8], fa[mi], bh4[nj][hb], bh4[nj][hb + 1]);
                }
        }
        buf = (buf + 1) & 3;
    }

    // epilogue
#pragma unroll
    for (int mi = 0; mi < 4; mi++) {
        size_t rowa = m0 + wm * 64 + mi * 16 + gr;
#pragma unroll
        for (int n8 = 0; n8 < 4; n8++) {
            int col = (int)n0 + wn * 32 + n8 * 8 + tg * 2;
            float b0v = bproj[col], b1v = bproj[col + 1];
            *(float2*)(out + rowa * CH + col) =
                make_float2(D[mi][n8][0] + b0v, D[mi][n8][1] + b1v);
            *(float2*)(out + (rowa + 8) * CH + col) =
                make_float2(D[mi][n8][2] + b0v, D[mi][n8][3] + b1v);
        }
    }
}

// ---------------- launch ----------------------------------------------------
extern "C" void kernel_launch(void* const* d_in, const int* in_sizes, int n_in,
                              void* d_out, int out_size)
{
    const float* x      = (const float*)d_in[0];
    const float* mask   = (const float*)d_in[1];
    const float* w_qkv  = (const float*)d_in[2];
    const float* b_qkv  = (const float*)d_in[3];
    const float* w_proj = (const float*)d_in[4];
    const float* b_proj = (const float*)d_in[5];
    const float* btab   = (const float*)d_in[6];
    float* out = (float*)d_out;

    __half *qkvh, *xh, *ath, *wqh, *wph;
    int* cnt;
    cudaGetSymbolAddress((void**)&qkvh, g_qkvh);
    cudaGetSymbolAddress((void**)&xh, g_xh);
    cudaGetSymbolAddress((void**)&ath, g_ath);
    cudaGetSymbolAddress((void**)&wqh, g_wqh);
    cudaGetSymbolAddress((void**)&wph, g_wph);
    cudaGetSymbolAddress((void**)&cnt, g_cnt);

    cudaFuncSetAttribute(gemm_mma, cudaFuncAttributeMaxDynamicSharedMemorySize,
                         GEMM_SMEM);
    cudaFuncSetAttribute(attn_proj, cudaFuncAttributeMaxDynamicSharedMemorySize,
                         FUSE_SMEM);

    // reset dependency counters (captured into the graph)
    cudaMemsetAsync(cnt, 0, BWT * sizeof(int));

    // prepass
    conv_h<<<(MROWS * KC) / (256 * 4), 256>>>(x, xh);
    transpose_h<<<dim3(N1 / 32, KC / 32), dim3(32, 8)>>>(w_qkv, wqh, KC, N1);
    transpose_h<<<dim3(CH / 32, KC / 32), dim3(32, 8)>>>(w_proj, wph, KC, CH);

    // GEMM1: qkv(fp16) = x @ w_qkv + b_qkv
    gemm_mma<<<dim3(N1 / 128, MROWS / 128), 128, GEMM_SMEM>>>(
        xh, wqh, b_qkv, qkvh, N1);
    // fused: attention (blocks 0..8191) + projection (blocks 8192..12287)
    attn_proj<<<12 * BWT, 256, FUSE_SMEM>>>(qkvh, mask, btab, ath, wph,
                                            b_proj, out);
}

// round 17
// speedup vs baseline: 1.0392x; 1.0392x over previous
#include <cuda_runtime.h>
#include <cuda_fp16.h>
#include <cstdint>
#include <cstddef>

// Problem constants
#define BWT   1024
#define WIN_  128
#define CH    512
#define NHH   8
#define HDD   64
#define MROWS (BWT * WIN_)   // 131072
#define N1    (3 * CH)       // 1536
#define KC    512

// ---------------- scratch (device globals) ----------------------------------
__device__ __half g_qkvh[(size_t)MROWS * N1];  // fp16 qkv (GEMM1 out, attn in)
__device__ __half g_xh[(size_t)MROWS * KC];    // fp16(x)
__device__ __half g_ath[(size_t)MROWS * CH];   // fp16 attention out (GEMM2 in)
__device__ __half g_wqh[(size_t)N1 * KC];      // fp16(w_qkv^T)  [N1][K]
__device__ __half g_wph[(size_t)CH * KC];      // fp16(w_proj^T) [CH][K]

// ---------------- helpers ----------------------------------------------------
__device__ __forceinline__ uint32_t smem_u32(const void* p) {
    uint32_t a;
    asm("{ .reg .u64 t; cvta.to.shared.u64 t, %1; cvt.u32.u64 %0, t; }" : "=r"(a) : "l"(p));
    return a;
}

#define CP_ASYNC16(dst, src) \
    asm volatile("cp.async.cg.shared.global [%0], [%1], 16;" :: "r"(dst), "l"(src) : "memory")
#define CP_COMMIT()  asm volatile("cp.async.commit_group;" ::: "memory")
#define CP_WAIT1()   asm volatile("cp.async.wait_group 1;" ::: "memory")
#define CP_WAIT0()   asm volatile("cp.async.wait_group 0;" ::: "memory")

#define LDM4(r0, r1, r2, r3, addr) \
    asm volatile("ldmatrix.sync.aligned.m8n8.x4.shared.b16 {%0,%1,%2,%3}, [%4];" \
        : "=r"(r0), "=r"(r1), "=r"(r2), "=r"(r3) : "r"(addr))
#define LDM4T(r0, r1, r2, r3, addr) \
    asm volatile("ldmatrix.sync.aligned.m8n8.x4.trans.shared.b16 {%0,%1,%2,%3}, [%4];" \
        : "=r"(r0), "=r"(r1), "=r"(r2), "=r"(r3) : "r"(addr))

#define MMA_F16(d, a, b0, b1) \
    asm volatile("mma.sync.aligned.m16n8k16.row.col.f32.f16.f16.f32 " \
        "{%0,%1,%2,%3}, {%4,%5,%6,%7}, {%8,%9}, {%0,%1,%2,%3};" \
        : "+f"((d)[0]), "+f"((d)[1]), "+f"((d)[2]), "+f"((d)[3]) \
        : "r"((a)[0]), "r"((a)[1]), "r"((a)[2]), "r"((a)[3]), "r"(b0), "r"(b1))

__device__ __forceinline__ uint32_t h2u(float a, float b) {
    __half2 h = __floats2half2_rn(a, b);
    return *(uint32_t*)&h;
}
__device__ __forceinline__ void store2(float* p, float a, float b) {
    *(float2*)p = make_float2(a, b);
}
__device__ __forceinline__ void store2(__half* p, float a, float b) {
    *(__half2*)p = __floats2half2_rn(a, b);
}

// ---------------- merged prepass: one launch ---------------------------------
// blocks [0, 65536):        conv x -> fp16          (256 thr, 1024 elems/blk)
// blocks [65536, 66304):    transpose w_qkv -> wqh  (48 x 16 tile grid)
// blocks [66304, 66560):    transpose w_proj -> wph (16 x 16 tile grid)
#define CONV_BLKS (MROWS * KC / 1024)          // 65536
#define WQ_BLKS   ((N1 / 32) * (KC / 32))      // 768
#define WP_BLKS   ((CH / 32) * (KC / 32))      // 256
#define PRE_BLKS  (CONV_BLKS + WQ_BLKS + WP_BLKS)

__global__ __launch_bounds__(256)
void prepass(const float* __restrict__ x, __half* __restrict__ xh,
             const float* __restrict__ wq, __half* __restrict__ wqh,
             const float* __restrict__ wpr, __half* __restrict__ wph)
{
    const int blk = blockIdx.x;
    if (blk < CONV_BLKS) {
        size_t i = ((size_t)blk * 256 + threadIdx.x) * 4;
        float4 v = *(const float4*)(x + i);
        __half h[4] = {__float2half_rn(v.x), __float2half_rn(v.y),
                       __float2half_rn(v.z), __float2half_rn(v.w)};
        *(uint2*)(xh + i) = *(uint2*)h;
        return;
    }

    // transpose role: W [K][N] -> Th [N][K] (fp16), 32x32 tiles
    __shared__ float t[32][33];
    const float* W;
    __half* Th;
    int N, tile;
    if (blk < CONV_BLKS + WQ_BLKS) {
        W = wq; Th = wqh; N = N1; tile = blk - CONV_BLKS;
    } else {
        W = wpr; Th = wph; N = CH; tile = blk - CONV_BLKS - WQ_BLKS;
    }
    const int ntiles = N / 32;
    const int nb = (tile % ntiles) * 32;
    const int kb = (tile / ntiles) * 32;
    const int tx = threadIdx.x & 31, ty = threadIdx.x >> 5;  // 32 x 8

    for (int i = ty; i < 32; i += 8)
        t[i][tx] = W[(size_t)(kb + i) * N + nb + tx];
    __syncthreads();
    for (int i = ty; i < 32; i += 8)
        Th[(size_t)(nb + i) * KC + kb + tx] = __float2half_rn(t[tx][i]);
}

// ---------------- fp16 HMMA GEMM: C[M,N] = A @ Bt^T + bias -------------------
// CTA 128x128, BK=64, 128 threads (4 warps, 2x2 grid, warp tile 64x64).
// 3-stage cp.async pipeline (32KB/stage), 2 CTAs/SM. (R11 measured-best config)
#define STAGE_B 32768
#define GEMM_SMEM (3 * STAGE_B)

template <typename OutT>
__global__ __launch_bounds__(128, 2)
void gemm_mma(const __half* __restrict__ Ah, const __half* __restrict__ Bh,
              const float* __restrict__ bias, OutT* __restrict__ C, int N)
{
    extern __shared__ char smem[];
    const uint32_t sbase = smem_u32(smem);
    const int tid = threadIdx.x;
    const int lane = tid & 31, wid = tid >> 5;
    const int wm = wid & 1, wn = wid >> 1;          // 2 x 2 warp grid
    const size_t m0 = (size_t)blockIdx.y * 128;
    const size_t n0 = (size_t)blockIdx.x * 128;

    const int r0 = tid >> 3, c = tid & 7;
    const __half* srcA = Ah + (m0 + r0) * KC + c * 8;
    const __half* srcB = Bh + (n0 + r0) * KC + c * 8;
    const uint32_t dstA = sbase + r0 * 128 + (uint32_t)((c ^ (r0 & 7)) << 4);
    const uint32_t dstB = dstA + 16384;

#define LOAD_PART(buf, k0, T0, T1) do {                                  \
        uint32_t so = (uint32_t)(buf) * STAGE_B;                         \
        _Pragma("unroll")                                                \
        for (int t = (T0); t < (T1); t++) {                              \
            CP_ASYNC16(dstA + so + t * 2048, srcA + (k0) + t * 16 * KC); \
            CP_ASYNC16(dstB + so + t * 2048, srcB + (k0) + t * 16 * KC); \
        }                                                                \
    } while (0)

    const int arow = wm * 64 + (lane & 15);
    const int brow_ = wn * 64 + (lane & 7) + ((lane >> 4) << 3);
#define LD_AFRAG(fa, stb, slab) do {                                       \
        _Pragma("unroll")                                                  \
        for (int mi = 0; mi < 4; mi++) {                                   \
            int row = arow + mi * 16;                                      \
            int kc = ((slab) << 1) + (lane >> 4);                          \
            LDM4((fa)[mi][0], (fa)[mi][1], (fa)[mi][2], (fa)[mi][3],       \
                 (stb) + row * 128 + ((kc ^ (row & 7)) << 4));             \
        }                                                                  \
    } while (0)
#define LD_BFRAG(bh, stb, slab) do {                                       \
        _Pragma("unroll")                                                  \
        for (int nj = 0; nj < 4; nj++) {                                   \
            int row = brow_ + nj * 16;                                     \
            int kc = ((slab) << 1) + ((lane >> 3) & 1);                    \
            LDM4((bh)[nj][0], (bh)[nj][1], (bh)[nj][2], (bh)[nj][3],       \
                 (stb) + 16384 + row * 128 + ((kc ^ (row & 7)) << 4));     \
        }                                                                  \
    } while (0)

    float D[4][8][4];
#pragma unroll
    for (int i = 0; i < 4; i++)
#pragma unroll
        for (int j = 0; j < 8; j++)
#pragma unroll
            for (int q = 0; q < 4; q++) D[i][j][q] = 0.0f;

    LOAD_PART(0, 0, 0, 8);  CP_COMMIT();
    LOAD_PART(1, 64, 0, 8); CP_COMMIT();

    uint32_t fa[2][4][4], fb[2][4][4];

    const int NSTAGE = KC / 64;   // 8
#pragma unroll 1
    for (int s = 0; s < NSTAGE; s++) {
        if (s + 1 < NSTAGE) { CP_WAIT1(); } else { CP_WAIT0(); }
        __syncthreads();

        int bufc = s; bufc -= (bufc >= 3) ? 3 : 0; bufc -= (bufc >= 3) ? 3 : 0;
        bufc -= (bufc >= 3) ? 3 : 0;
        const uint32_t stb = sbase + (uint32_t)bufc * STAGE_B;

        const bool havenext = (s + 2 < NSTAGE);
        int nb = s + 2; nb -= (nb >= 3) ? 3 : 0; nb -= (nb >= 3) ? 3 : 0;
        const int nk0 = (s + 2) * 64;

        LD_BFRAG(fb[0], stb, 0);
        LD_AFRAG(fa[0], stb, 0);
        if (havenext) LOAD_PART(nb, nk0, 0, 4);

#pragma unroll
        for (int slab = 0; slab < 4; slab++) {
            const int cur = slab & 1, nxt = cur ^ 1;
            if (slab < 3) {
                LD_BFRAG(fb[nxt], stb, slab + 1);
                LD_AFRAG(fa[nxt], stb, slab + 1);
            }
#pragma unroll
            for (int mi = 0; mi < 4; mi++)
#pragma unroll
                for (int n8 = 0; n8 < 8; n8++) {
                    const int nj = n8 >> 1, hb = (n8 & 1) * 2;
                    MMA_F16(D[mi][n8], fa[cur][mi], fb[cur][nj][hb], fb[cur][nj][hb + 1]);
                }
            if (slab == 0 && havenext) { LOAD_PART(nb, nk0, 4, 8); CP_COMMIT(); }
        }
    }

    const int gr = lane >> 2, tg = lane & 3;
#pragma unroll
    for (int mi = 0; mi < 4; mi++) {
        size_t rowa = m0 + wm * 64 + mi * 16 + gr;
#pragma unroll
        for (int n8 = 0; n8 < 8; n8++) {
            int col = (int)n0 + wn * 64 + n8 * 8 + tg * 2;
            float b0v = bias[col], b1v = bias[col + 1];
            store2(C + rowa * N + col, D[mi][n8][0] + b0v, D[mi][n8][1] + b1v);
            store2(C + (rowa + 8) * N + col, D[mi][n8][2] + b0v, D[mi][n8][3] + b1v);
        }
    }
}

// ---------------- HMMA window attention: one CTA per (head, window) ----------
// 8 warps x 16 q-rows; 2 CTAs/SM. Max-free softmax (scores tightly bounded).
#define ATTN_SMEM (3 * 16384 + 1024)

__global__ __launch_bounds__(256, 2)
void attn_mma(const __half* __restrict__ qkv, const float* __restrict__ mask,
              const float* __restrict__ btab, __half* __restrict__ att)
{
    const int h = blockIdx.x;
    const int b = blockIdx.y;
    const int tid = threadIdx.x;
    const int lane = tid & 31, w = tid >> 5;
    const int gr = lane >> 2, tg = lane & 3;

    extern __shared__ char smc[];
    const uint32_t Qb = smem_u32(smc);
    const uint32_t Kb = Qb + 16384;
    const uint32_t Vb = Qb + 32768;
    float* bs = (float*)(smc + 49152);

    const size_t grow0 = (size_t)b * WIN_;
#pragma unroll
    for (int i = 0; i < 4; i++) {
        int g = tid + 256 * i;
        int r = g >> 3, c = g & 7;
        const __half* src = qkv + (grow0 + r) * N1 + h * HDD + c * 8;
        uint32_t doff = r * 128 + (uint32_t)((c ^ (r & 7)) << 4);
        CP_ASYNC16(Qb + doff, src);
        CP_ASYNC16(Kb + doff, src + CH);
        CP_ASYNC16(Vb + doff, src + 2 * CH);
    }
    CP_COMMIT();
    if (tid < 255) bs[tid] = btab[tid * NHH + h];
    CP_WAIT0();
    __syncthreads();

    const int m0 = w * 16;
    const int r_lo = m0 + gr, r_hi = m0 + gr + 8;

    // ---- S = Q K^T ----
    float D[16][4];
#pragma unroll
    for (int j = 0; j < 16; j++)
#pragma unroll
        for (int c2 = 0; c2 < 4; c2++) D[j][c2] = 0.0f;

#pragma unroll
    for (int s = 0; s < 4; s++) {
        uint32_t a[4];
        {
            int row = m0 + (lane & 15);
            int kc = (s << 1) + (lane >> 4);
            LDM4(a[0], a[1], a[2], a[3], Qb + row * 128 + ((kc ^ (row & 7)) << 4));
        }
#pragma unroll
        for (int jj = 0; jj < 8; jj++) {
            uint32_t v0, v1, v2, v3;
            int grp = lane >> 3;
            int nrow = jj * 16 + ((grp >> 1) & 1) * 8 + (lane & 7);
            int kc = (s << 1) + (grp & 1);
            LDM4(v0, v1, v2, v3, Kb + nrow * 128 + ((kc ^ (nrow & 7)) << 4));
            MMA_F16(D[2 * jj], a, v0, v1);
            MMA_F16(D[2 * jj + 1], a, v2, v3);
        }
    }

    // ---- scale + rel-pos bias + window mask, then exp (no max shift) ----
    const float* mrow = mask + (size_t)(b & 63) * (WIN_ * WIN_);
    uint32_t Pk[16][2];
    float slo = 0.0f, shi = 0.0f;
#pragma unroll
    for (int j = 0; j < 16; j++) {
        int c = 8 * j + 2 * tg;
        float2 mlo2 = *(const float2*)(mrow + r_lo * 128 + c);
        float2 mhi2 = *(const float2*)(mrow + r_hi * 128 + c);
        float e0 = __expf(D[j][0] * 0.125f + bs[c - r_lo + 127] + mlo2.x);
        float e1 = __expf(D[j][1] * 0.125f + bs[c + 1 - r_lo + 127] + mlo2.y);
        float e2 = __expf(D[j][2] * 0.125f + bs[c - r_hi + 127] + mhi2.x);
        float e3 = __expf(D[j][3] * 0.125f + bs[c + 1 - r_hi + 127] + mhi2.y);
        slo += e0 + e1;
        shi += e2 + e3;
        Pk[j][0] = h2u(e0, e1);
        Pk[j][1] = h2u(e2, e3);
    }
    slo += __shfl_xor_sync(0xffffffffu, slo, 1);
    slo += __shfl_xor_sync(0xffffffffu, slo, 2);
    shi += __shfl_xor_sync(0xffffffffu, shi, 1);
    shi += __shfl_xor_sync(0xffffffffu, shi, 2);
    const float invlo = 1.0f / slo, invhi = 1.0f / shi;

    // ---- O = P V ----
    float O[8][4];
#pragma unroll
    for (int j = 0; j < 8; j++)
#pragma unroll
        for (int c2 = 0; c2 < 4; c2++) O[j][c2] = 0.0f;

#pragma unroll
    for (int s = 0; s < 8; s++) {
        uint32_t a[4];
        a[0] = Pk[2 * s][0];
        a[1] = Pk[2 * s][1];
        a[2] = Pk[2 * s + 1][0];
        a[3] = Pk[2 * s + 1][1];
#pragma unroll
        for (int jj = 0; jj < 4; jj++) {
            uint32_t v0, v1, v2, v3;
            int grp = lane >> 3;
            int krow = 16 * s + (grp & 1) * 8 + (lane & 7);
            int nc = (jj << 1) + ((grp >> 1) & 1);
            LDM4T(v0, v1, v2, v3, Vb + krow * 128 + ((nc ^ (krow & 7)) << 4));
            MMA_F16(O[2 * jj], a, v0, v1);
            MMA_F16(O[2 * jj + 1], a, v2, v3);
        }
    }

    __half* ob = att + grow0 * CH + h * HDD;
#pragma unroll
    for (int j = 0; j < 8; j++) {
        int c = 8 * j + 2 * tg;
        *(__half2*)(ob + (size_t)r_lo * CH + c) =
            __floats2half2_rn(O[j][0] * invlo, O[j][1] * invlo);
        *(__half2*)(ob + (size_t)r_hi * CH + c) =
            __floats2half2_rn(O[j][2] * invhi, O[j][3] * invhi);
    }
}

// ---------------- launch ----------------------------------------------------
extern "C" void kernel_launch(void* const* d_in, const int* in_sizes, int n_in,
                              void* d_out, int out_size)
{
    const float* x      = (const float*)d_in[0];
    const float* mask   = (const float*)d_in[1];
    const float* w_qkv  = (const float*)d_in[2];
    const float* b_qkv  = (const float*)d_in[3];
    const float* w_proj = (const float*)d_in[4];
    const float* b_proj = (const float*)d_in[5];
    const float* btab   = (const float*)d_in[6];
    float* out = (float*)d_out;

    __half *qkvh, *xh, *ath, *wqh, *wph;
    cudaGetSymbolAddress((void**)&qkvh, g_qkvh);
    cudaGetSymbolAddress((void**)&xh, g_xh);
    cudaGetSymbolAddress((void**)&ath, g_ath);
    cudaGetSymbolAddress((void**)&wqh, g_wqh);
    cudaGetSymbolAddress((void**)&wph, g_wph);

    cudaFuncSetAttribute(gemm_mma<__half>, cudaFuncAttributeMaxDynamicSharedMemorySize,
                         GEMM_SMEM);
    cudaFuncSetAttribute(gemm_mma<float>, cudaFuncAttributeMaxDynamicSharedMemorySize,
                         GEMM_SMEM);
    cudaFuncSetAttribute(attn_mma, cudaFuncAttributeMaxDynamicSharedMemorySize,
                         ATTN_SMEM);

    // merged prepass: x->fp16 + both weight transposes in ONE launch
    prepass<<<PRE_BLKS, 256>>>(x, xh, w_qkv, wqh, w_proj, wph);

    // GEMM1: qkv(fp16) = x @ w_qkv + b_qkv
    gemm_mma<__half><<<dim3(N1 / 128, MROWS / 128), 128, GEMM_SMEM>>>(
        xh, wqh, b_qkv, qkvh, N1);
    // attention (fp16 out)
    attn_mma<<<dim3(NHH, BWT), 256, ATTN_SMEM>>>(qkvh, mask, btab, ath);
    // GEMM2: out(fp32) = att @ w_proj + b_proj
    gemm_mma<float><<<dim3(CH / 128, MROWS / 128), 128, GEMM_SMEM>>>(
        ath, wph, b_proj, out, CH);
}